// round 16
// baseline (speedup 1.0000x reference)
#include <cuda_runtime.h>
#include <cstddef>

#define LSEQ 256
#define NB   8
#define NC   64
#define PTOT 37120   // padded row-layout size (rs(255) = 36607)
#define DPAD 512     // slack for discarded-lane bulk reads

// t = max_c scores, padded-row layout: g_td[b*PTOT + rs(i) + (e-i-1)]
__device__ float g_td[NB * PTOT];

// Bank-aligned row starts, closed form: rs(i) % 32 == i % 32.
__host__ __device__ __forceinline__ int rs_pad(int i) {
    const int q = i >> 5, k = i & 31;
    const int g = (k <= 30) ? ((k * (k + 3)) >> 1) : 495;
    return i * 255 - ((i * (i - 1)) >> 1) + 496 * q + g;
}

// ---------------------------------------------------------------------------
// Kernel 1: t[b,i,e] = max over C of scores[b,i,e,:], upper triangle only.
// ---------------------------------------------------------------------------
__global__ void max_kernel(const float* __restrict__ scores) {
    const int i    = blockIdx.x;          // 0 .. 254
    const int b    = blockIdx.y;
    const int warp = threadIdx.x >> 5;
    const int lane = threadIdx.x & 31;
    const int base = b * PTOT + rs_pad(i) - i - 1;

    for (int e = i + 1 + warp; e < LSEQ; e += 8) {
        const float* p = scores + (((size_t)b * LSEQ + i) * LSEQ + e) * NC;
        float v = fmaxf(p[lane], p[lane + 32]);
        #pragma unroll
        for (int o = 16; o > 0; o >>= 1)
            v = fmaxf(v, __shfl_xor_sync(0xffffffffu, v, o));
        if (lane == 0)
            g_td[base + e] = v;
    }
}

// ---------------------------------------------------------------------------
// Kernel 2: CKY inside (max semiring), one 1024-thread CTA per batch,
// EIGHT widths per pass (32 passes), software-pipelined tail.
//
// Per pass P (base width w, widths w..w+7):
//  Phase 1 (concurrent):
//   - warps 8-19 (384 thr): bulk widths w..w+3,  j in [16, w-9]
//   - warps 20-31 (384 thr): bulk widths w+4..w+7, same j range
//     (children have widths <= w-9: complete before tail(P-1) began, and
//      disjoint from the diagonals w-8..w-1 the tail writes concurrently)
//   - warps 0-7 (256 thr): tail(P-1): ordered terms j in [1,d] and
//     [wprev, wd-1], merged with VV(P-1), + t, stored. Then prefetch t.
//  Phase 2 (all 1024, 2 slots each): VV = G-reduce of bulk partials +
//    old-safe boundary terms j in [d+1, min(15,w-1)] and [max(16,w-8), w-1].
// Coverage: [1,d]+[d+1,15]+[16,w-9]+[w-8,w-1]+[w,wd-1] = [1,wd-1].
// ---------------------------------------------------------------------------
__global__ __launch_bounds__(1024, 1)
void dp_kernel(const int* __restrict__ lens, float* __restrict__ out) {
    const int b = blockIdx.x;
    extern __shared__ float S[];
    float* D  = S;                          // PTOT + DPAD chart
    float* P0 = S + PTOT + DPAD;            // 8 x 384 bulk partials (d-major)
    float* VV = P0 + 8 * 384;               // 8 x 256 pre-combined
    int*   rs = (int*)(VV + 2048);          // padded row starts
    const float* tb  = g_td + b * PTOT;
    const int    tid = threadIdx.x;

    if (tid < 256) rs[tid] = rs_pad(tid);
    __syncthreads();
    if (tid < 255) D[rs[tid]] = tb[rs[tid]];        // width-1 diagonal
    __syncthreads();

    // Tail-thread state
    int   rsc = 0, lim = 0;
    float tt[8];
    #pragma unroll
    for (int q = 0; q < 8; ++q) tt[q] = 0.f;
    if (tid < 256) {
        rsc = rs[tid];
        lim = rsc + (tid < 254 ? 254 - tid : 0);
        #pragma unroll
        for (int q = 0; q < 8; ++q) {            // t for widths 2..9
            int ix = rsc + 1 + q;
            tt[q] = tb[ix < lim ? ix : lim];
        }
    }
    __syncthreads();

    int wprev = 0;
    for (int w = 2; w < LSEQ; w += 8) {
        const int n = LSEQ - w;
        // 384-thread group tiers
        int M, G;
        if      (n > 128) { M = 384; G = 1;  }
        else if (n > 64)  { M = 128; G = 3;  }
        else if (n > 32)  { M = 64;  G = 6;  }
        else              { M = 32;  G = 12; }
        const int m = w - 24;                 // count of bulk range [16, w-9]

        // ================= Phase 1 (concurrent) =================
        if (tid >= 256) {
            const int grp   = (tid >= 640);           // 0: d=0..3, 1: d=4..7
            const int idx   = tid - 256 - (grp << 9) + (grp << 7); // -384*grp
            const int dbase = grp << 2;
            int c, g;
            if (G == 1) { c = idx;           g = 0; }
            else        { c = idx & (M - 1); g = idx / M; }
            float a0 = -1e30f, a1 = -1e30f, a2 = -1e30f, a3 = -1e30f;
            if (c < n && m > 0) {
                const int jlo = 16 + (g * m) / G;
                const int jhi = 16 + ((g + 1) * m) / G;
                if (jlo < jhi) {
                    const int lb = rs[c] - 1;          // left: D[lb + j]
                    int tp = c + jlo;
                    int rb = w - jlo - 1 + dbase;      // right col base
                    #pragma unroll 4
                    for (int j = jlo; j < jhi; ++j) {
                        const float L  = D[lb + j];
                        const int   ra = rs[tp] + rb;
                        a0 = fmaxf(a0, L + D[ra]);
                        a1 = fmaxf(a1, L + D[ra + 1]);
                        a2 = fmaxf(a2, L + D[ra + 2]);
                        a3 = fmaxf(a3, L + D[ra + 3]);
                        ++tp; --rb;
                    }
                }
            }
            P0[(dbase    ) * 384 + idx] = a0;
            P0[(dbase + 1) * 384 + idx] = a1;
            P0[(dbase + 2) * 384 + idx] = a2;
            P0[(dbase + 3) * 384 + idx] = a3;
        } else {
            // ---- tail(P-1): ordered terms + store (skipped on first pass)
            if (w > 2) {
                #pragma unroll
                for (int d = 0; d < 8; ++d) {
                    const int wd = wprev + d;
                    if (wd <= 255 && tid < LSEQ - wd) {
                        float v = VV[(d << 8) + tid];
                        #pragma unroll
                        for (int j = 1; j <= 7; ++j)       // j in [1, d]
                            if (j <= d)
                                v = fmaxf(v, D[rsc + j - 1] +
                                             D[rs[tid + j] + wd - j - 1]);
                        #pragma unroll
                        for (int e = 0; e < 7; ++e)        // j = wprev+e, e<d
                            if (e < d)
                                v = fmaxf(v, D[rsc + wprev + e - 1] +
                                             D[rs[tid + wprev + e] + d - e - 1]);
                        D[rsc + wd - 1] = v + tt[d];
                    }
                    asm volatile("bar.sync 1, 256;" ::: "memory");
                }
            }
            // prefetch t for pass P's widths w..w+7 (consumed next pass)
            #pragma unroll
            for (int q = 0; q < 8; ++q) {
                int ix = rsc + w + q - 1;
                tt[q] = tb[ix < lim ? ix : lim];
            }
        }
        __syncthreads();

        // ================= Phase 2: pre-combine (all 1024, 2 slots) ========
        #pragma unroll
        for (int h = 0; h < 2; ++h) {
            const int slot = tid + (h << 10);
            const int d    = slot >> 8;
            const int cc   = slot & 255;
            const int wd   = w + d;
            float v = -1e30f;
            if (wd <= 255 && cc < LSEQ - wd) {
                const float* PP = P0 + d * 384;
                if (m > 0)
                    for (int g = 0; g < G; ++g)
                        v = fmaxf(v, PP[g * M + cc]);
                const int rcb = rs[cc];
                // old-safe low: j in [d+1, min(15, w-1)]
                const int jtop = (w - 1 < 15) ? w - 1 : 15;
                for (int j = d + 1; j <= jtop; ++j)
                    v = fmaxf(v, D[rcb + j - 1] +
                                 D[rs[cc + j] + wd - j - 1]);
                // old-safe high: j in [max(16, w-8), w-1]
                const int jh = (w - 8 > 16) ? w - 8 : 16;
                #pragma unroll
                for (int e = 0; e < 8; ++e) {
                    const int j = jh + e;
                    if (j < w)
                        v = fmaxf(v, D[rcb + j - 1] +
                                     D[rs[cc + j] + wd - j - 1]);
                }
            }
            VV[slot] = v;
        }
        __syncthreads();
        wprev = w;
    }

    // ---- final tail: wprev = 250 (widths 250..255)
    if (tid < 256) {
        #pragma unroll
        for (int d = 0; d < 8; ++d) {
            const int wd = 250 + d;
            if (wd <= 255 && tid < LSEQ - wd) {
                float v = VV[(d << 8) + tid];
                #pragma unroll
                for (int j = 1; j <= 7; ++j)
                    if (j <= d)
                        v = fmaxf(v, D[rsc + j - 1] +
                                     D[rs[tid + j] + wd - j - 1]);
                #pragma unroll
                for (int e = 0; e < 7; ++e)
                    if (e < d)
                        v = fmaxf(v, D[rsc + 250 + e - 1] +
                                     D[rs[tid + 250 + e] + d - e - 1]);
                D[rsc + wd - 1] = v + tt[d];
            }
            asm volatile("bar.sync 1, 256;" ::: "memory");
        }
    }
    __syncthreads();

    if (tid == 0) {
        int len = lens[b];
        len = len < 1 ? 1 : (len > 255 ? 255 : len);
        out[b] = D[len - 1];                 // s[0, len] = row 0, col len-1
    }
}

// ---------------------------------------------------------------------------
extern "C" void kernel_launch(void* const* d_in, const int* in_sizes, int n_in,
                              void* d_out, int out_size) {
    const float* scores = (const float*)d_in[0];
    const int*   lens   = (const int*)d_in[1];
    float*       out    = (float*)d_out;
    (void)in_sizes; (void)n_in; (void)out_size;

    const int smem = (PTOT + DPAD + 8 * 384 + 2048 + 256) * (int)sizeof(float);
    cudaFuncSetAttribute(dp_kernel,
                         cudaFuncAttributeMaxDynamicSharedMemorySize, smem);

    max_kernel<<<dim3(LSEQ - 1, NB), 256>>>(scores);
    dp_kernel<<<NB, 1024, smem>>>(lens, out);
}

// round 17
// speedup vs baseline: 1.0674x; 1.0674x over previous
#include <cuda_runtime.h>
#include <cstddef>

#define LSEQ 256
#define NB   8
#define NC   64
#define PTOT 37120   // padded row-layout size (rs(255) = 36607)
#define DPAD 512     // slack for discarded-lane bulk reads

// t = max_c scores, padded-row layout: g_td[b*PTOT + rs(i) + (e-i-1)]
__device__ float g_td[NB * PTOT];

// Bank-aligned row starts, closed form: rs(i) % 32 == i % 32.
__host__ __device__ __forceinline__ int rs_pad(int i) {
    const int q = i >> 5, k = i & 31;
    const int g = (k <= 30) ? ((k * (k + 3)) >> 1) : 495;
    return i * 255 - ((i * (i - 1)) >> 1) + 496 * q + g;
}

// ---------------------------------------------------------------------------
// Kernel 1: t[b,i,e] = max over C of scores[b,i,e,:], upper triangle only.
// ---------------------------------------------------------------------------
__global__ void max_kernel(const float* __restrict__ scores) {
    const int i    = blockIdx.x;          // 0 .. 254
    const int b    = blockIdx.y;
    const int warp = threadIdx.x >> 5;
    const int lane = threadIdx.x & 31;
    const int base = b * PTOT + rs_pad(i) - i - 1;

    for (int e = i + 1 + warp; e < LSEQ; e += 8) {
        const float* p = scores + (((size_t)b * LSEQ + i) * LSEQ + e) * NC;
        float v = fmaxf(p[lane], p[lane + 32]);
        #pragma unroll
        for (int o = 16; o > 0; o >>= 1)
            v = fmaxf(v, __shfl_xor_sync(0xffffffffu, v, o));
        if (lane == 0)
            g_td[base + e] = v;
    }
}

// ---------------------------------------------------------------------------
// Kernel 2: CKY inside (max semiring), one 1024-thread CTA per batch,
// 4 widths per pass, pipelined tail + WEIGHTED j-split:
//  Phase 1: warps 8-31 run bulk(P) (j in [8, w-5], weight 5 per group);
//           warps 0-7 run tail(P-1) (ordered fixups, hidden), prefetch t,
//           then ALSO compute a small bulk chunk (weight 1 per group).
//  Phase 2 (all 1024): VV(P) = reduce all group partials + old-safe boundary
//           terms j in [d+1, min(7,w-1)] and [max(8,w-4), w-1].
// Coverage: [1,d]+[d+1,7]+[8,w-5]+[w-4,w-1]+[w,wd-1] = [1,wd-1].
// Bulk reads only diags <= w-5; tail writes diags w-4..w-1 — disjoint.
// ---------------------------------------------------------------------------
__global__ __launch_bounds__(1024, 1)
void dp_kernel(const int* __restrict__ lens, float* __restrict__ out) {
    const int b = blockIdx.x;
    extern __shared__ float S[];
    float* D  = S;                          // PTOT + DPAD chart
    float* P0 = S + PTOT + DPAD;            // 4 x 1024 bulk partials
    float* VV = P0 + 4 * 1024;              // 4 x 256 pre-combined
    int*   rs = (int*)(VV + 1024);          // padded row starts
    const float* tb  = g_td + b * PTOT;
    const int    tid = threadIdx.x;

    if (tid < 256) rs[tid] = rs_pad(tid);
    __syncthreads();
    if (tid < 255) D[rs[tid]] = tb[rs[tid]];        // width-1 diagonal
    __syncthreads();

    // Tail-thread state
    int   rsc = 0, lim = 0;
    float tt0 = 0.f, tt1 = 0.f, tt2 = 0.f, tt3 = 0.f;
    if (tid < 256) {
        rsc = rs[tid];
        lim = rsc + (tid < 254 ? 254 - tid : 0);
    }

    int wprev = 0;
    for (int w = 2; w < LSEQ; w += 4) {
        const int n  = LSEQ - w;
        const int sM = (n > 128) ? 8 : (n > 64) ? 7 : (n > 32) ? 6 : 5;
        const int nb = 768 >> sM;             // bulk groups (weight 5)
        const int qshift = 12 - sM;           // denom = 16*256/M = 1<<qshift
        const int m  = w - 12;                // count of bulk range [8, w-5]

        // ================= Phase 1 =================
        // Tail(P-1) first (warps 0-7); bulk threads skip straight to bulk.
        if (tid < 256) {
            if (w > 2) {
                #pragma unroll
                for (int d = 0; d < 4; ++d) {
                    const int wd = wprev + d;     // wprev <= w-4 <= 250
                    if (tid < LSEQ - wd) {
                        float v = VV[(d << 8) + tid];
                        #pragma unroll
                        for (int j = 1; j <= 3; ++j)      // j in [1, d]
                            if (j <= d)
                                v = fmaxf(v, D[rsc + j - 1] +
                                             D[rs[tid + j] + wd - j - 1]);
                        #pragma unroll
                        for (int e = 0; e < 3; ++e)       // j in [wprev, wd-1]
                            if (e < d)
                                v = fmaxf(v, D[rsc + wprev + e - 1] +
                                             D[rs[tid + wprev + e] + d - e - 1]);
                        const float tv = (d == 0) ? tt0 : (d == 1) ? tt1
                                       : (d == 2) ? tt2 : tt3;
                        D[rsc + wd - 1] = v + tv;
                    }
                    asm volatile("bar.sync 1, 256;" ::: "memory");
                }
            }
            // prefetch t for pass P's widths w..w+3 (consumed next pass)
            const int i0 = rsc + w - 1;
            tt0 = tb[i0     < lim ? i0     : lim];
            tt1 = tb[i0 + 1 < lim ? i0 + 1 : lim];
            tt2 = tb[i0 + 2 < lim ? i0 + 2 : lim];
            tt3 = tb[i0 + 3 < lim ? i0 + 3 : lim];
        }

        // ---- bulk (all threads; tail threads take a 1-quantum chunk)
        {
            int vidx, q0, q1;
            if (tid >= 256) {                    // weight-5 groups
                vidx = tid - 256;
                const int g = vidx >> sM;
                q0 = 5 * g; q1 = q0 + 5;
            } else {                             // weight-1 groups
                vidx = 768 + tid;
                const int g = tid >> sM;
                q0 = 5 * nb + g; q1 = q0 + 1;
            }
            const int c = vidx & ((1 << sM) - 1);
            float a0 = -1e30f, a1 = -1e30f, a2 = -1e30f, a3 = -1e30f;
            if (c < n && m > 0) {
                const int jlo = 8 + ((q0 * m) >> qshift);
                const int jhi = 8 + ((q1 * m) >> qshift);
                if (jlo < jhi) {
                    const int lb = rs[c] - 1;    // left: D[lb + j]
                    int tp = c + jlo;
                    int rb = w - jlo - 1;
                    #pragma unroll 4
                    for (int j = jlo; j < jhi; ++j) {
                        const float L  = D[lb + j];
                        const int   ra = rs[tp] + rb;
                        a0 = fmaxf(a0, L + D[ra]);
                        a1 = fmaxf(a1, L + D[ra + 1]);
                        a2 = fmaxf(a2, L + D[ra + 2]);
                        a3 = fmaxf(a3, L + D[ra + 3]);
                        ++tp; --rb;
                    }
                }
            }
            P0[vidx]        = a0;
            P0[1024 + vidx] = a1;
            P0[2048 + vidx] = a2;
            P0[3072 + vidx] = a3;
        }
        __syncthreads();

        // ================= Phase 2: pre-combine (all 1024) =================
        {
            const int d  = tid >> 8;
            const int cc = tid & 255;
            const int wd = w + d;
            float v = -1e30f;
            if (wd <= 255 && cc < LSEQ - wd) {
                const int M = 1 << sM;
                const int G = 1024 >> sM;
                const float* PP = P0 + (d << 10);
                if (m > 0)
                    for (int g = 0; g < G; ++g)
                        v = fmaxf(v, PP[g * M + cc]);
                const int rcb = rs[cc];
                // old-safe low terms: j in [d+1, min(7, w-1)]
                #pragma unroll
                for (int j = 1; j <= 7; ++j)
                    if (j > d && j < w)
                        v = fmaxf(v, D[rcb + j - 1] +
                                     D[rs[cc + j] + wd - j - 1]);
                // old-safe high terms: j in [max(8, w-4), w-1]
                const int j2 = (w - 4 > 8) ? w - 4 : 8;
                #pragma unroll
                for (int e = 0; e < 4; ++e) {
                    const int j = j2 + e;
                    if (j < w)
                        v = fmaxf(v, D[rcb + j - 1] +
                                     D[rs[cc + j] + wd - j - 1]);
                }
            }
            VV[tid] = v;                          // tid == (d<<8)+cc
        }
        __syncthreads();
        wprev = w;
    }

    // ---- final tail: wprev = 254 (widths 254, 255)
    if (tid < 256) {
        #pragma unroll
        for (int d = 0; d < 2; ++d) {
            const int wd = 254 + d;
            if (tid < LSEQ - wd) {
                float v = VV[(d << 8) + tid];
                if (d == 1) {
                    v = fmaxf(v, D[rsc] + D[rs[tid + 1] + wd - 2]);     // j=1
                    v = fmaxf(v, D[rsc + 253] + D[rs[tid + 254]]);      // j=254
                }
                const float tv = (d == 0) ? tt0 : tt1;
                D[rsc + wd - 1] = v + tv;
            }
            asm volatile("bar.sync 1, 256;" ::: "memory");
        }
    }
    __syncthreads();

    if (tid == 0) {
        int len = lens[b];
        len = len < 1 ? 1 : (len > 255 ? 255 : len);
        out[b] = D[len - 1];                 // s[0, len] = row 0, col len-1
    }
}

// ---------------------------------------------------------------------------
extern "C" void kernel_launch(void* const* d_in, const int* in_sizes, int n_in,
                              void* d_out, int out_size) {
    const float* scores = (const float*)d_in[0];
    const int*   lens   = (const int*)d_in[1];
    float*       out    = (float*)d_out;
    (void)in_sizes; (void)n_in; (void)out_size;

    const int smem = (PTOT + DPAD + 4 * 1024 + 1024 + 256) * (int)sizeof(float);
    cudaFuncSetAttribute(dp_kernel,
                         cudaFuncAttributeMaxDynamicSharedMemorySize, smem);

    max_kernel<<<dim3(LSEQ - 1, NB), 256>>>(scores);
    dp_kernel<<<NB, 1024, smem>>>(lens, out);
}